// round 17
// baseline (speedup 1.0000x reference)
#include <cuda_runtime.h>
#include <cuda_fp16.h>
#include <stdint.h>

// Problem constants (fixed by the dataset)
#define BATCH   1024
#define IN_DIM  1024
#define OUT_DIM 40960
#define FANIN   7

// Tiling
#define BTILE      64             // 32 half2-interleaved pair-rows
#define NPAIR      32
#define XS2_STRIDE 1025           // half2 units per pair-row; 1025%32==1
#define THREADS    1024
#define WARPS      32
#define CHUNK_O    256            // o per work item (8 o per warp)
#define O_PER_WARP 8
#define OBLK       (OUT_DIM / CHUNK_O)        // 160
#define NB         (BATCH / BTILE)            // 16
#define N_ITEMS    (NB * OBLK)                // 2560
#define N_CTA      148

#define XS_SLOTS     (NPAIR * XS2_STRIDE)     // 32800 half2 = 131200 B
#define STG2_STRIDE  33                       // float2 per o row (32 + pad)
#define QUAD_STG_F2  (32 * STG2_STRIDE)       // 1056 float2 per quad
#define NQUADS       (WARPS / 4)              // 8
#define SMEM_FLOATS  (XS_SLOTS + NQUADS * QUAD_STG_F2 * 2)
#define SMEM_BYTES   (SMEM_FLOATS * 4)        // 198784 B

// Quad-scoped named barrier (4 warps = 128 threads). HW barriers 1..8 only;
// barrier 0 reserved for __syncthreads (refills) — mixed arrival counts on
// one barrier ID are UB.
#define QUAD_BAR(q) \
    asm volatile("bar.sync %0, 128;" :: "r"((q) + 1) : "memory")

// Packed per-output metadata: 48B = uint4 (7x u16 idx*4 = half2 byte offset)
// + 7 f32 vals + pad. vals stay fp32 (only gathered x is fp16).
__device__ __align__(16) uint4 g_meta[OUT_DIM * 3];

__global__ void prep_kernel(const int* __restrict__ idx,
                            const float* __restrict__ vals) {
    int o = blockIdx.x * blockDim.x + threadIdx.x;
    if (o >= OUT_DIM) return;
    unsigned id[FANIN];
    float v[FANIN];
#pragma unroll
    for (int k = 0; k < FANIN; k++) {
        id[k] = (unsigned)idx[o * FANIN + k] * 4u;   // half2 byte offset <=4092
        v[k]  = vals[o * FANIN + k];
    }
    uint4 mi, ma, mb;
    mi.x = id[0] | (id[1] << 16);
    mi.y = id[2] | (id[3] << 16);
    mi.z = id[4] | (id[5] << 16);
    mi.w = id[6];
    ma.x = __float_as_uint(v[0]); ma.y = __float_as_uint(v[1]);
    ma.z = __float_as_uint(v[2]); ma.w = __float_as_uint(v[3]);
    mb.x = __float_as_uint(v[4]); mb.y = __float_as_uint(v[5]);
    mb.z = __float_as_uint(v[6]); mb.w = 0u;
    uint4* dst = g_meta + (size_t)o * 3;
    dst[0] = mi; dst[1] = ma; dst[2] = mb;
}

// Dual-row dot: xb2 = this lane's pair-row base (byte ptr into half2 tile).
// Each gather is LDS.32 (one half2 = rows 2p,2p+1); bank = p + idx mod 32,
// all 32 lanes distinct -> conflict-free for ANY idx. Accumulate in fp32.
__device__ __forceinline__ float2 dot7x2h(const char* xb2, uint4 mi, uint4 ma,
                                          uint4 mb) {
    float2 g0 = __half22float2(*reinterpret_cast<const __half2*>(xb2 + (mi.x & 0xFFFFu)));
    float2 g1 = __half22float2(*reinterpret_cast<const __half2*>(xb2 + (mi.x >> 16)));
    float2 g2 = __half22float2(*reinterpret_cast<const __half2*>(xb2 + (mi.y & 0xFFFFu)));
    float2 g3 = __half22float2(*reinterpret_cast<const __half2*>(xb2 + (mi.y >> 16)));
    float2 g4 = __half22float2(*reinterpret_cast<const __half2*>(xb2 + (mi.z & 0xFFFFu)));
    float2 g5 = __half22float2(*reinterpret_cast<const __half2*>(xb2 + (mi.z >> 16)));
    float2 g6 = __half22float2(*reinterpret_cast<const __half2*>(xb2 + (mi.w & 0xFFFFu)));
    float v0 = __uint_as_float(ma.x), v1 = __uint_as_float(ma.y);
    float v2 = __uint_as_float(ma.z), v3 = __uint_as_float(ma.w);
    float v4 = __uint_as_float(mb.x), v5 = __uint_as_float(mb.y);
    float v6 = __uint_as_float(mb.z);
    float2 r;
    {
        float s0 = fmaf(v0, g0.x, v1 * g1.x);
        float s1 = fmaf(v2, g2.x, v3 * g3.x);
        float s2 = fmaf(v4, g4.x, v5 * g5.x);
        r.x = (s0 + s1) + (s2 + v6 * g6.x);
    }
    {
        float s0 = fmaf(v0, g0.y, v1 * g1.y);
        float s1 = fmaf(v2, g2.y, v3 * g3.y);
        float s2 = fmaf(v4, g4.y, v5 * g5.y);
        r.y = (s0 + s1) + (s2 + v6 * g6.y);
    }
    return r;
}

// Fill half2-interleaved x tile: xs2[p][i] = half2(x[2p][i], x[2p+1][i]).
// Task (p, c4): p = (warp&7)*4 + (lane>>3), c4 = it*32 + (warp>>3)*8 + (lane&7).
// LDG: 8 consecutive lanes read 128B contiguous per row -> coalesced.
// STS.32 banks = (p + 4*c4 + j) mod 32: over warp = l2 + 4*b3 + const -> all
// 32 distinct -> conflict-free.
__device__ __forceinline__ void fill_x(const float* __restrict__ x,
                                       __half2* xs2, int b0) {
    const float4* xg = reinterpret_cast<const float4*>(x + (size_t)b0 * IN_DIM);
    const int lane = threadIdx.x & 31;
    const int warp = threadIdx.x >> 5;
    const int p  = ((warp & 7) << 2) | ((lane >> 3) & 3);
    const int cb = ((warp >> 3) << 3) | (lane & 7);
#pragma unroll
    for (int h = 0; h < 2; h++) {
        float4 va[4], vb[4];
#pragma unroll
        for (int t = 0; t < 4; t++) {
            int c4 = ((h * 4 + t) << 5) | cb;
            va[t] = xg[(2 * p)     * (IN_DIM / 4) + c4];
            vb[t] = xg[(2 * p + 1) * (IN_DIM / 4) + c4];
        }
#pragma unroll
        for (int t = 0; t < 4; t++) {
            int c4 = ((h * 4 + t) << 5) | cb;
            __half2* d = xs2 + p * XS2_STRIDE + 4 * c4;
            d[0] = __floats2half2_rn(va[t].x, vb[t].x);  // low = row 2p
            d[1] = __floats2half2_rn(va[t].y, vb[t].y);
            d[2] = __floats2half2_rn(va[t].z, vb[t].z);
            d[3] = __floats2half2_rn(va[t].w, vb[t].w);
        }
    }
}

extern __shared__ float smem_all[];
// layout: [32800 slots] x-tile half2 | [8][1056 float2] staging

__global__ __launch_bounds__(THREADS, 1)
void mb_proj_kernel(const float* __restrict__ x, float* __restrict__ y) {
    __half2* xs2 = reinterpret_cast<__half2*>(smem_all);
    float2* stg_base = reinterpret_cast<float2*>(smem_all + XS_SLOTS);

    // Persistent static partition, b-major item order (item = b*160 + oblk)
    // -> <=1 b-boundary crossing -> <=2 x fills per CTA.
    const int istart = (int)((long)blockIdx.x * N_ITEMS / N_CTA);
    const int iend   = (int)((long)(blockIdx.x + 1) * N_ITEMS / N_CTA);

    int cur_b = istart / OBLK;
    fill_x(x, xs2, cur_b * BTILE);
    __syncthreads();

    const int warp = threadIdx.x >> 5;
    const int lane = threadIdx.x & 31;
    const int quad = warp >> 2;
    const int wq   = warp & 3;

    // Gather base: lane = pair-row p (4100 B per pair-row).
    const char* xb2 = reinterpret_cast<const char*>(xs2)
                    + lane * (XS2_STRIDE * 4);
    float2* stgq = stg_base + quad * QUAD_STG_F2;

    // Meta comes straight from gmem (L2-resident) via uniform LDG.128 with
    // distance-1 rotation: each iteration's 3 loads are covered by ~500
    // warp-cycles of issue ahead of use (>> 262-cyc L2 latency). No smem.
    const uint4* gm = g_meta
        + (size_t)((istart % OBLK) * CHUNK_O + warp * O_PER_WARP) * 3;
    uint4 c0 = gm[0], c1 = gm[1], c2 = gm[2];

    for (int item = istart; item < iend; item++) {
        const int b_idx = item / OBLK;
        const int oblk  = item - b_idx * OBLK;

        // Refill x tile on b-boundary (CTA-uniform branch; <=1 per CTA).
        if (b_idx != cur_b) {
            __syncthreads();
            fill_x(x, xs2, b_idx * BTILE);
            cur_b = b_idx;
            __syncthreads();
        }

        // Next item's meta base (rotation tail preloads its first record,
        // giving it the whole store phase + barriers to land).
        const int nitem = (item + 1 < iend) ? item + 1 : item;
        const uint4* gm_next = g_meta
            + (size_t)((nitem % OBLK) * CHUNK_O + warp * O_PER_WARP) * 3;

        // ---- Compute: 8 o (uniform per warp) x 64 b ---------------------
        // Staging STS.64 float2 at [o_loc*33 + p]: banks 2p+{0,1} -> exactly
        // 2 words/bank = 2 wf = 256B floor.
        {
#pragma unroll
            for (int s = 0; s < O_PER_WARP; s++) {
                const uint4* np = (s < O_PER_WARP - 1) ? (gm + 3 * (s + 1))
                                                       : gm_next;
                uint4 n0 = np[0], n1 = np[1], n2 = np[2];
                float2 r = dot7x2h(xb2, c0, c1, c2);
                stgq[(wq * O_PER_WARP + s) * STG2_STRIDE + lane] = r;
                c0 = n0; c1 = n1; c2 = n2;
            }
        }
        gm = gm_next;

        QUAD_BAR(quad);   // quad's staging tile complete

        // ---- Store quad tile: 32 o x 64 b -------------------------------
        // lane = o. Warp wq handles pair-rows pp = wq*8 + ip. LDS.64 banks
        // 2*lane+{0,1} -> 2 words/bank = floor. Each STG.32 row = 128B
        // contiguous, 32-o aligned -> 1 wf.
        {
            const int o_quad = oblk * CHUNK_O + quad * 32;
            float* ybase = y + (size_t)(cur_b * BTILE) * OUT_DIM + o_quad + lane;
#pragma unroll
            for (int ip = 0; ip < 8; ip++) {
                const int pp = wq * 8 + ip;
                float2 r2 = stgq[lane * STG2_STRIDE + pp];
                ybase[(size_t)(2 * pp)     * OUT_DIM] = r2.x;
                ybase[(size_t)(2 * pp + 1) * OUT_DIM] = r2.y;
            }
        }

        QUAD_BAR(quad);   // quad done reading staging -> safe to reuse
    }
}

extern "C" void kernel_launch(void* const* d_in, const int* in_sizes, int n_in,
                              void* d_out, int out_size) {
    const float* x    = (const float*)d_in[0];   // [1024, 1024] f32
    const float* vals = (const float*)d_in[1];   // [40960, 7]   f32
    const int*   idx  = (const int*)d_in[2];     // [40960, 7]   i32
    float*       y    = (float*)d_out;           // [1024, 40960] f32

    (void)in_sizes; (void)n_in; (void)out_size;

    cudaFuncSetAttribute(mb_proj_kernel,
                         cudaFuncAttributeMaxDynamicSharedMemorySize, SMEM_BYTES);

    prep_kernel<<<(OUT_DIM + 255) / 256, 256>>>(idx, vals);

    mb_proj_kernel<<<N_CTA, THREADS, SMEM_BYTES>>>(x, y);
}